// round 13
// baseline (speedup 1.0000x reference)
#include <cuda_runtime.h>
#include <cuda_fp16.h>
#include <cstdint>

// ============================================================================
// DoubleGRU on sm_100 (portable ISA): 13 chained 128x128x128 GEMMs per
// 128-row tile using mma.sync.m16n8k16 fp16 (fp32 accum).
// R13: single live accumulator (reordered gates, rh/r2h in RH smem tile),
// explicitly double-buffered fragment k-loop (LDSM k+1 overlaps MMA k),
// MUFU.TANH epilogues, one __syncthreads per GEMM. 512 thr, m32n32 tiles.
// ============================================================================

#define THREADS 512
#define NTILES  1024
#define AST     136                  // tile stride (fp16 elems, padded)
#define TILE_BYTES (128 * AST * 2)   // 34816

// ---- smem layout (bytes) ----
#define SM_BIAS 0                        // 768 floats
#define SM_X    4096
#define SM_H    (SM_X + TILE_BYTES)
#define SM_Z    (SM_H + TILE_BYTES)
#define SM_RH   (SM_Z + TILE_BYTES)
#define SM_W0   (SM_RH + TILE_BYTES)
#define SM_W1   (SM_W0 + TILE_BYTES)
#define SM_TOTAL (SM_W1 + TILE_BYTES)    // 212992

// GEMM g uses weight slot WSLOT[g] (see schedule in kernel body).
// slots: 0-2 Wx1[i], 3-5 Wx2[i], 6-11 Wh[i], 12 mid
__device__ constexpr int WSLOT[13] = {1, 7, 0, 6, 2, 8, 12, 4, 10, 3, 6, 5, 11};

// Pre-transposed ([n][k], padded to AST) fp16 weight images.
__device__ __align__(256) __half g_w[13][128 * AST];

// ============================== PTX helpers ==============================
__device__ __forceinline__ uint32_t smem_to_u32(const void* p) {
    uint32_t a;
    asm("{ .reg .u64 t; cvta.to.shared.u64 t, %1; cvt.u32.u64 %0, t; }" : "=r"(a) : "l"(p));
    return a;
}

#define WAITG1 asm volatile("cp.async.wait_group 1;" ::: "memory")
#define WAITG0 asm volatile("cp.async.wait_group 0;" ::: "memory")
#define COMMITG asm volatile("cp.async.commit_group;" ::: "memory")

__device__ __forceinline__ void cp_async16(uint32_t dst, const void* src) {
    asm volatile("cp.async.cg.shared.global [%0], [%1], 16;" :: "r"(dst), "l"(src) : "memory");
}

__device__ __forceinline__ void ldm4(uint32_t* r, uint32_t addr) {
    asm volatile("ldmatrix.sync.aligned.m8n8.x4.shared.b16 {%0,%1,%2,%3}, [%4];"
        : "=r"(r[0]), "=r"(r[1]), "=r"(r[2]), "=r"(r[3]) : "r"(addr));
}

__device__ __forceinline__ void mma16816(float* c, const uint32_t* a, const uint32_t* b) {
    asm volatile("mma.sync.aligned.m16n8k16.row.col.f32.f16.f16.f32 "
        "{%0,%1,%2,%3}, {%4,%5,%6,%7}, {%8,%9}, {%0,%1,%2,%3};"
        : "+f"(c[0]), "+f"(c[1]), "+f"(c[2]), "+f"(c[3])
        : "r"(a[0]), "r"(a[1]), "r"(a[2]), "r"(a[3]), "r"(b[0]), "r"(b[1]));
}

// ============================== small math ==============================
__device__ __forceinline__ float tanh_f(float v) {
    float r;
    asm("tanh.approx.f32 %0, %1;" : "=f"(r) : "f"(v));
    return r;
}
__device__ __forceinline__ float sigm_f(float v) {
    return fmaf(tanh_f(v * 0.5f), 0.5f, 0.5f);
}
__device__ __forceinline__ float2 h2f(uint32_t u) {
    __half2 t = *reinterpret_cast<__half2*>(&u);
    return __half22float2(t);
}

// fp16 tile: load/store fp32 pair (col even)
__device__ __forceinline__ float2 lds_f(uint32_t base, int row, int col) {
    uint32_t off = (uint32_t)((row * AST + col) * 2);
    uint32_t h;
    asm volatile("ld.shared.u32 %0, [%1];" : "=r"(h) : "r"(base + off));
    return h2f(h);
}
__device__ __forceinline__ void sts_f(uint32_t base, int row, int col, float2 v) {
    __half2 hb = __float22half2_rn(v);
    uint32_t off = (uint32_t)((row * AST + col) * 2);
    uint32_t hu = *reinterpret_cast<uint32_t*>(&hb);
    asm volatile("st.shared.u32 [%0], %1;" :: "r"(base + off), "r"(hu) : "memory");
}

// ======================= weight prep (fp32 -> fp16, [n][k] padded) =======================
__global__ void prep_weights(const float* __restrict__ wx1, const float* __restrict__ wx2,
                             const float* __restrict__ wh, const float* __restrict__ mid) {
    int idx = blockIdx.x * blockDim.x + threadIdx.x;
    if (idx >= 13 * 128 * AST) return;
    int slot = idx / (128 * AST);
    int r = idx % (128 * AST);
    int n = r / AST;
    int k = r % AST;
    float v = 0.0f;
    if (k < 128) {
        const float* src;
        if (slot < 3)       src = wx1 + slot * 16384;
        else if (slot < 6)  src = wx2 + (slot - 3) * 16384;
        else if (slot < 12) src = wh + (slot - 6) * 16384;
        else                src = mid;
        v = src[k * 128 + n];   // W[k][n] -> B[n][k]
    }
    g_w[slot][n * AST + k] = __float2half_rn(v);
}

// ======================= GEMM (m32n32 warp tile, frag double-buffer) =======================
// fA[buf][0..3] = A rows [0,16), fA[buf][4..7] = A rows [16,32)
// fB[buf][0..3] = B cols [0,16), fB[buf][4..7] = B cols [16,32)
__device__ __forceinline__ void gemm_single(uint32_t aT, uint32_t bB, float (*acc)[4][4]) {
    uint32_t fA[2][8], fB[2][8];
    ldm4(fA[0] + 0, aT);
    ldm4(fA[0] + 4, aT + 16 * AST * 2);
    ldm4(fB[0] + 0, bB);
    ldm4(fB[0] + 4, bB + 16 * AST * 2);
#pragma unroll
    for (int k = 0; k < 8; k++) {
        const int cur = k & 1, nxt = cur ^ 1;
        if (k < 7) {
            ldm4(fA[nxt] + 0, aT + (k + 1) * 32);
            ldm4(fA[nxt] + 4, aT + 16 * AST * 2 + (k + 1) * 32);
            ldm4(fB[nxt] + 0, bB + (k + 1) * 32);
            ldm4(fB[nxt] + 4, bB + 16 * AST * 2 + (k + 1) * 32);
        }
        mma16816(acc[0][0], fA[cur] + 0, fB[cur] + 0);
        mma16816(acc[0][1], fA[cur] + 0, fB[cur] + 2);
        mma16816(acc[0][2], fA[cur] + 0, fB[cur] + 4);
        mma16816(acc[0][3], fA[cur] + 0, fB[cur] + 6);
        mma16816(acc[1][0], fA[cur] + 4, fB[cur] + 0);
        mma16816(acc[1][1], fA[cur] + 4, fB[cur] + 2);
        mma16816(acc[1][2], fA[cur] + 4, fB[cur] + 4);
        mma16816(acc[1][3], fA[cur] + 4, fB[cur] + 6);
    }
}

__device__ __forceinline__ void issue_chunk(uint32_t sb, const __half* src,
                                            int tid, int buf) {
    uint32_t dst = sb + (buf ? SM_W1 : SM_W0);
    const char* g = (const char*)src;
#pragma unroll
    for (int off = 0; off < TILE_BYTES; off += THREADS * 16) {
        int o = off + tid * 16;
        if (o < TILE_BYTES) cp_async16(dst + o, g + o);
    }
    COMMITG;
}

__device__ __forceinline__ void zero_acc(float (*acc)[4][4]) {
#pragma unroll
    for (int i = 0; i < 2; i++)
#pragma unroll
        for (int j = 0; j < 4; j++)
#pragma unroll
            for (int e = 0; e < 4; e++) acc[i][j][e] = 0.0f;
}

// ================================ main kernel ================================
__global__ void __launch_bounds__(THREADS, 1)
dgru_kernel(const float* __restrict__ x, const float* __restrict__ h_in,
            const float* __restrict__ bias_g, float* __restrict__ out) {
    extern __shared__ char smem[];
    uint32_t sb = smem_to_u32(smem);
    int tid  = threadIdx.x;
    int lane = tid & 31;
    int wid  = tid >> 5;
    int wm   = wid & 3;    // warp m block (32 rows)
    int wn   = wid >> 2;   // warp n block (32 cols)
    int tile = blockIdx.x;

    // kick off first two weight chunks immediately (chunk g -> buf g&1)
    issue_chunk(sb, &g_w[WSLOT[0]][0], tid, 0);
    issue_chunk(sb, &g_w[WSLOT[1]][0], tid, 1);

    // bias -> smem
    float* bias = (float*)(smem + SM_BIAS);
    for (int i = tid; i < 768; i += THREADS) bias[i] = bias_g[i];

    // prologue: x, old_h -> fp16 tiles (each thread: 1 row x 32 cols)
    {
        int prow = tid >> 2, half = (tid & 3) * 32;
        const float4* px = (const float4*)(x    + ((size_t)tile * 128 + prow) * 128 + half);
        const float4* ph = (const float4*)(h_in + ((size_t)tile * 128 + prow) * 128 + half);
#pragma unroll
        for (int c4 = 0; c4 < 8; c4++) {
            float4 v = px[c4];
            sts_f(sb + SM_X, prow, half + c4 * 4,     make_float2(v.x, v.y));
            sts_f(sb + SM_X, prow, half + c4 * 4 + 2, make_float2(v.z, v.w));
            float4 u = ph[c4];
            sts_f(sb + SM_H, prow, half + c4 * 4,     make_float2(u.x, u.y));
            sts_f(sb + SM_H, prow, half + c4 * 4 + 2, make_float2(u.z, u.w));
        }
    }

    // per-thread ldmatrix base offsets (bytes within a tile)
    int aro = (lane & 7) + ((lane >> 3) & 1) * 8;
    int ako = ((lane >> 4) & 1) * 8;
    int bro = (lane & 7) + ((lane >> 4) & 1) * 8;
    int bko = ((lane >> 3) & 1) * 8;
    uint32_t aoff = (uint32_t)(((wm * 32 + aro) * AST + ako) * 2);
    uint32_t boff = (uint32_t)(((wn * 32 + bro) * AST + bko) * 2);

    float acc[2][4][4];   // single live accumulator set

    // epilogue element coordinates
    int erow = wm * 32 + (lane >> 2);        // + i*16 (+8 for regs 2,3)
    int ecol = wn * 32 + (lane & 3) * 2;     // + j*8
    float* otile = out + (size_t)tile * 128 * 128;

    // One GEMM per step, ONE sync per step. Entry sync proves all warps are
    // done with GEMM g-1 (which read buf (g-1)&1 = (g+1)&1), so we refill that
    // buffer with chunk g+1 here, then wait for chunk g (one group back).
#define GEMM_STEP(ATILE, G) do {                                                \
        __syncthreads();                                                        \
        if ((G) >= 1 && (G) <= 11) issue_chunk(sb, &g_w[WSLOT[(G) + 1]][0], tid, ((G) + 1) & 1); \
        if ((G) < 12) { WAITG1; } else { WAITG0; }                              \
        gemm_single(sb + (ATILE) + aoff,                                        \
                    sb + (((G) & 1) ? SM_W1 : SM_W0) + boff, acc);              \
    } while (0)

    // ================= stage 1 =================
    // r = sg(x@Wx1[1] + h@Wh[1] + b1); rh = r*old_h -> RH
    zero_acc(acc);
    GEMM_STEP(SM_X, 0);                  // x  @ Wx1[1]
    GEMM_STEP(SM_H, 1);                  // h  @ Wh[1]
#pragma unroll
    for (int i = 0; i < 2; i++)
#pragma unroll
        for (int j = 0; j < 4; j++) {
            int r0 = erow + i * 16, c = ecol + j * 8;
            float2 oh0 = lds_f(sb + SM_H, r0, c);
            float2 oh1 = lds_f(sb + SM_H, r0 + 8, c);
            sts_f(sb + SM_RH, r0, c,
                  make_float2(sigm_f(acc[i][j][0] + bias[128 + c]) * oh0.x,
                              sigm_f(acc[i][j][1] + bias[128 + c + 1]) * oh0.y));
            sts_f(sb + SM_RH, r0 + 8, c,
                  make_float2(sigm_f(acc[i][j][2] + bias[128 + c]) * oh1.x,
                              sigm_f(acc[i][j][3] + bias[128 + c + 1]) * oh1.y));
        }

    // z = sg(x@Wx1[0] + h@Wh[0] + b0) -> Z
    zero_acc(acc);
    GEMM_STEP(SM_X, 2);                  // x  @ Wx1[0]
    GEMM_STEP(SM_H, 3);                  // h  @ Wh[0]
#pragma unroll
    for (int i = 0; i < 2; i++)
#pragma unroll
        for (int j = 0; j < 4; j++) {
            int r0 = erow + i * 16, c = ecol + j * 8;
            sts_f(sb + SM_Z, r0, c, make_float2(sigm_f(acc[i][j][0] + bias[c]),
                                                sigm_f(acc[i][j][1] + bias[c + 1])));
            sts_f(sb + SM_Z, r0 + 8, c, make_float2(sigm_f(acc[i][j][2] + bias[c]),
                                                    sigm_f(acc[i][j][3] + bias[c + 1])));
        }

    // h~ = tanh(x@Wx1[2] + rh@Wh[2] + b2); mid_h = z*old_h + (1-z)*h~ -> H
    zero_acc(acc);
    GEMM_STEP(SM_X, 4);                  // x  @ Wx1[2]
    GEMM_STEP(SM_RH, 5);                 // rh @ Wh[2]
#pragma unroll
    for (int i = 0; i < 2; i++)
#pragma unroll
        for (int j = 0; j < 4; j++) {
            int r0 = erow + i * 16, c = ecol + j * 8;
#pragma unroll
            for (int half = 0; half < 2; half++) {
                int r = r0 + half * 8;
                float2 oh = lds_f(sb + SM_H, r, c);
                float2 z  = lds_f(sb + SM_Z, r, c);
                float ht0 = tanh_f(acc[i][j][2 * half]     + bias[256 + c]);
                float ht1 = tanh_f(acc[i][j][2 * half + 1] + bias[256 + c + 1]);
                sts_f(sb + SM_H, r, c,
                      make_float2(z.x * oh.x + (1.0f - z.x) * ht0,
                                  z.y * oh.y + (1.0f - z.y) * ht1));
            }
        }

    // mid_x = relu(mid_h @ mid) -> X
    zero_acc(acc);
    GEMM_STEP(SM_H, 6);                  // mid_h @ mid
#pragma unroll
    for (int i = 0; i < 2; i++)
#pragma unroll
        for (int j = 0; j < 4; j++) {
            int r0 = erow + i * 16, c = ecol + j * 8;
            sts_f(sb + SM_X, r0, c,
                  make_float2(fmaxf(acc[i][j][0], 0.0f), fmaxf(acc[i][j][1], 0.0f)));
            sts_f(sb + SM_X, r0 + 8, c,
                  make_float2(fmaxf(acc[i][j][2], 0.0f), fmaxf(acc[i][j][3], 0.0f)));
        }

    // ================= stage 2 =================
    // r2 = sg(mid_x@Wx2[1] + mid_h@Wh[4] + b4); r2h = r2*mid_h -> RH
    zero_acc(acc);
    GEMM_STEP(SM_X, 7);                  // mid_x @ Wx2[1]
    GEMM_STEP(SM_H, 8);                  // mid_h @ Wh[4]
#pragma unroll
    for (int i = 0; i < 2; i++)
#pragma unroll
        for (int j = 0; j < 4; j++) {
            int r0 = erow + i * 16, c = ecol + j * 8;
            float2 mh0 = lds_f(sb + SM_H, r0, c);
            float2 mh1 = lds_f(sb + SM_H, r0 + 8, c);
            sts_f(sb + SM_RH, r0, c,
                  make_float2(sigm_f(acc[i][j][0] + bias[512 + c]) * mh0.x,
                              sigm_f(acc[i][j][1] + bias[512 + c + 1]) * mh0.y));
            sts_f(sb + SM_RH, r0 + 8, c,
                  make_float2(sigm_f(acc[i][j][2] + bias[512 + c]) * mh1.x,
                              sigm_f(acc[i][j][3] + bias[512 + c + 1]) * mh1.y));
        }

    // z2 = sg(mid_x@Wx2[0] + mid_h@Wh[0] + b0) -> Z
    zero_acc(acc);
    GEMM_STEP(SM_X, 9);                  // mid_x @ Wx2[0]
    GEMM_STEP(SM_H, 10);                 // mid_h @ Wh[0]
#pragma unroll
    for (int i = 0; i < 2; i++)
#pragma unroll
        for (int j = 0; j < 4; j++) {
            int r0 = erow + i * 16, c = ecol + j * 8;
            sts_f(sb + SM_Z, r0, c, make_float2(sigm_f(acc[i][j][0] + bias[c]),
                                                sigm_f(acc[i][j][1] + bias[c + 1])));
            sts_f(sb + SM_Z, r0 + 8, c, make_float2(sigm_f(acc[i][j][2] + bias[c]),
                                                    sigm_f(acc[i][j][3] + bias[c + 1])));
        }

    // h2~ = tanh(mid_x@Wx2[2] + r2h@Wh[5] + b5); h = z2*mid_h + (1-z2)*h2~ -> OUT
    zero_acc(acc);
    GEMM_STEP(SM_X, 11);                 // mid_x @ Wx2[2]
    GEMM_STEP(SM_RH, 12);                // r2h  @ Wh[5]
#pragma unroll
    for (int i = 0; i < 2; i++)
#pragma unroll
        for (int j = 0; j < 4; j++) {
            int r0 = erow + i * 16, c = ecol + j * 8;
#pragma unroll
            for (int half = 0; half < 2; half++) {
                int r = r0 + half * 8;
                float2 mh = lds_f(sb + SM_H, r, c);
                float2 z  = lds_f(sb + SM_Z, r, c);
                float t0 = tanh_f(acc[i][j][2 * half]     + bias[640 + c]);
                float t1 = tanh_f(acc[i][j][2 * half + 1] + bias[640 + c + 1]);
                float2 h = make_float2(z.x * mh.x + (1.0f - z.x) * t0,
                                       z.y * mh.y + (1.0f - z.y) * t1);
                *(float2*)(otile + (size_t)r * 128 + c) = h;
            }
        }
#undef GEMM_STEP
}

// ================================ launch ================================
extern "C" void kernel_launch(void* const* d_in, const int* in_sizes, int n_in,
                              void* d_out, int out_size) {
    const float* x   = (const float*)d_in[0];
    const float* oh  = (const float*)d_in[1];
    const float* wx1 = (const float*)d_in[2];
    const float* wx2 = (const float*)d_in[3];
    const float* wh  = (const float*)d_in[4];
    const float* b   = (const float*)d_in[5];
    const float* mid = (const float*)d_in[6];
    float* out = (float*)d_out;

    cudaFuncSetAttribute(dgru_kernel, cudaFuncAttributeMaxDynamicSharedMemorySize, SM_TOTAL);
    prep_weights<<<(13 * 128 * AST + 255) / 256, 256>>>(wx1, wx2, wh, mid);
    dgru_kernel<<<NTILES, THREADS, SM_TOTAL>>>(x, oh, b, out);
}

// round 14
// speedup vs baseline: 1.0354x; 1.0354x over previous
#include <cuda_runtime.h>
#include <cuda_fp16.h>
#include <cstdint>

// ============================================================================
// DoubleGRU on sm_100 (portable ISA): 13 chained 128x128x128 GEMMs per
// 128-row tile using mma.sync.m16n8k16 fp16 (fp32 accum).
// R14: R12 core k-loop (reverted from R13's manual pipeline), fused dual-GEMM
// sync regions for the 4 accumulate-pairs, z gates in registers, 4-buffer
// weight ring. 512 threads, m32n32 warp tiles.
// ============================================================================

#define THREADS 512
#define NTILES  1024
#define AST     136                  // tile stride (fp16 elems, padded)
#define TILE_BYTES (128 * AST * 2)   // 34816

// ---- smem layout (bytes) ----
#define SM_BIAS  0                       // 768 floats
#define SM_X     4096
#define SM_H     (SM_X + TILE_BYTES)
#define SM_WBASE (SM_H + TILE_BYTES)
#define SM_TOTAL (SM_WBASE + 4 * TILE_BYTES)   // 212992

// chunk order c0..c12 -> weight slot (slots: 0-2 Wx1, 3-5 Wx2, 6-11 Wh, 12 mid)
__device__ constexpr int WSLOT[13] = {2, 0, 6, 1, 7, 8, 12, 5, 3, 6, 4, 10, 11};

// Pre-transposed ([n][k], padded to AST) fp16 weight images.
__device__ __align__(256) __half g_w[13][128 * AST];

// ============================== PTX helpers ==============================
__device__ __forceinline__ uint32_t smem_to_u32(const void* p) {
    uint32_t a;
    asm("{ .reg .u64 t; cvta.to.shared.u64 t, %1; cvt.u32.u64 %0, t; }" : "=r"(a) : "l"(p));
    return a;
}

#define WAITG3 asm volatile("cp.async.wait_group 3;" ::: "memory")
#define WAITG2 asm volatile("cp.async.wait_group 2;" ::: "memory")
#define WAITG1 asm volatile("cp.async.wait_group 1;" ::: "memory")
#define WAITG0 asm volatile("cp.async.wait_group 0;" ::: "memory")
#define COMMITG asm volatile("cp.async.commit_group;" ::: "memory")

__device__ __forceinline__ void cp_async16(uint32_t dst, const void* src) {
    asm volatile("cp.async.cg.shared.global [%0], [%1], 16;" :: "r"(dst), "l"(src) : "memory");
}

__device__ __forceinline__ void ldm4(uint32_t* r, uint32_t addr) {
    asm volatile("ldmatrix.sync.aligned.m8n8.x4.shared.b16 {%0,%1,%2,%3}, [%4];"
        : "=r"(r[0]), "=r"(r[1]), "=r"(r[2]), "=r"(r[3]) : "r"(addr));
}

__device__ __forceinline__ void mma16816(float* c, const uint32_t* a, const uint32_t* b) {
    asm volatile("mma.sync.aligned.m16n8k16.row.col.f32.f16.f16.f32 "
        "{%0,%1,%2,%3}, {%4,%5,%6,%7}, {%8,%9}, {%0,%1,%2,%3};"
        : "+f"(c[0]), "+f"(c[1]), "+f"(c[2]), "+f"(c[3])
        : "r"(a[0]), "r"(a[1]), "r"(a[2]), "r"(a[3]), "r"(b[0]), "r"(b[1]));
}

// ============================== small math ==============================
__device__ __forceinline__ float tanh_f(float v) {
    float r;
    asm("tanh.approx.f32 %0, %1;" : "=f"(r) : "f"(v));
    return r;
}
__device__ __forceinline__ float sigm_f(float v) {
    return fmaf(tanh_f(v * 0.5f), 0.5f, 0.5f);
}
__device__ __forceinline__ float2 h2f(uint32_t u) {
    __half2 t = *reinterpret_cast<__half2*>(&u);
    return __half22float2(t);
}

// fp16 tile: load/store fp32 pair (col even)
__device__ __forceinline__ float2 lds_f(uint32_t base, int row, int col) {
    uint32_t off = (uint32_t)((row * AST + col) * 2);
    uint32_t h;
    asm volatile("ld.shared.u32 %0, [%1];" : "=r"(h) : "r"(base + off));
    return h2f(h);
}
__device__ __forceinline__ void sts_f(uint32_t base, int row, int col, float2 v) {
    __half2 hb = __float22half2_rn(v);
    uint32_t off = (uint32_t)((row * AST + col) * 2);
    uint32_t hu = *reinterpret_cast<uint32_t*>(&hb);
    asm volatile("st.shared.u32 [%0], %1;" :: "r"(base + off), "r"(hu) : "memory");
}

// ======================= weight prep (fp32 -> fp16, [n][k] padded) =======================
__global__ void prep_weights(const float* __restrict__ wx1, const float* __restrict__ wx2,
                             const float* __restrict__ wh, const float* __restrict__ mid) {
    int idx = blockIdx.x * blockDim.x + threadIdx.x;
    if (idx >= 13 * 128 * AST) return;
    int slot = idx / (128 * AST);
    int r = idx % (128 * AST);
    int n = r / AST;
    int k = r % AST;
    float v = 0.0f;
    if (k < 128) {
        const float* src;
        if (slot < 3)       src = wx1 + slot * 16384;
        else if (slot < 6)  src = wx2 + (slot - 3) * 16384;
        else if (slot < 12) src = wh + (slot - 6) * 16384;
        else                src = mid;
        v = src[k * 128 + n];   // W[k][n] -> B[n][k]
    }
    g_w[slot][n * AST + k] = __float2half_rn(v);
}

// ======================= GEMM cores (m32n32 warp tile) =======================
// Simple per-k loop (R12-proven form): 4 ldm4 + 8 MMA per k.
__device__ __forceinline__ void gemm_single(uint32_t aT, uint32_t bB, float (*acc)[4][4]) {
#pragma unroll
    for (int k = 0; k < 8; k++) {
        uint32_t A0[4], A1[4], B0[4], B1[4];
        ldm4(A0, aT + k * 32);
        ldm4(A1, aT + 16 * AST * 2 + k * 32);
        ldm4(B0, bB + k * 32);
        ldm4(B1, bB + 16 * AST * 2 + k * 32);
        mma16816(acc[0][0], A0, B0);
        mma16816(acc[0][1], A0, B0 + 2);
        mma16816(acc[0][2], A0, B1);
        mma16816(acc[0][3], A0, B1 + 2);
        mma16816(acc[1][0], A1, B0);
        mma16816(acc[1][1], A1, B0 + 2);
        mma16816(acc[1][2], A1, B1);
        mma16816(acc[1][3], A1, B1 + 2);
    }
}

// Fused dual accumulate: acc += A1@B1 + A2@B2, one k-loop, 8 ldm4 + 16 MMA per k.
__device__ __forceinline__ void gemm_dual(uint32_t a1, uint32_t b1,
                                          uint32_t a2, uint32_t b2, float (*acc)[4][4]) {
#pragma unroll
    for (int k = 0; k < 8; k++) {
        uint32_t P0[4], P1[4], Q0[4], Q1[4];
        uint32_t R0[4], R1[4], S0[4], S1[4];
        ldm4(P0, a1 + k * 32);
        ldm4(P1, a1 + 16 * AST * 2 + k * 32);
        ldm4(Q0, b1 + k * 32);
        ldm4(Q1, b1 + 16 * AST * 2 + k * 32);
        ldm4(R0, a2 + k * 32);
        ldm4(R1, a2 + 16 * AST * 2 + k * 32);
        ldm4(S0, b2 + k * 32);
        ldm4(S1, b2 + 16 * AST * 2 + k * 32);
        mma16816(acc[0][0], P0, Q0);
        mma16816(acc[0][1], P0, Q0 + 2);
        mma16816(acc[0][2], P0, Q1);
        mma16816(acc[0][3], P0, Q1 + 2);
        mma16816(acc[1][0], P1, Q0);
        mma16816(acc[1][1], P1, Q0 + 2);
        mma16816(acc[1][2], P1, Q1);
        mma16816(acc[1][3], P1, Q1 + 2);
        mma16816(acc[0][0], R0, S0);
        mma16816(acc[0][1], R0, S0 + 2);
        mma16816(acc[0][2], R0, S1);
        mma16816(acc[0][3], R0, S1 + 2);
        mma16816(acc[1][0], R1, S0);
        mma16816(acc[1][1], R1, S0 + 2);
        mma16816(acc[1][2], R1, S1);
        mma16816(acc[1][3], R1, S1 + 2);
    }
}

__device__ __forceinline__ void issue_chunk(uint32_t sb, const __half* src,
                                            int tid, int buf) {
    uint32_t dst = sb + SM_WBASE + (uint32_t)buf * TILE_BYTES;
    const char* g = (const char*)src;
#pragma unroll
    for (int off = 0; off < TILE_BYTES; off += THREADS * 16) {
        int o = off + tid * 16;
        if (o < TILE_BYTES) cp_async16(dst + o, g + o);
    }
    COMMITG;
}

__device__ __forceinline__ void zero_acc(float (*acc)[4][4]) {
#pragma unroll
    for (int i = 0; i < 2; i++)
#pragma unroll
        for (int j = 0; j < 4; j++)
#pragma unroll
            for (int e = 0; e < 4; e++) acc[i][j][e] = 0.0f;
}

// ================================ main kernel ================================
__global__ void __launch_bounds__(THREADS, 1)
dgru_kernel(const float* __restrict__ x, const float* __restrict__ h_in,
            const float* __restrict__ bias_g, float* __restrict__ out) {
    extern __shared__ char smem[];
    uint32_t sb = smem_to_u32(smem);
    int tid  = threadIdx.x;
    int lane = tid & 31;
    int wid  = tid >> 5;
    int wm   = wid & 3;    // warp m block (32 rows)
    int wn   = wid >> 2;   // warp n block (32 cols)
    int tile = blockIdx.x;

    // kick off first four weight chunks (chunk c -> buf c)
    issue_chunk(sb, &g_w[WSLOT[0]][0], tid, 0);
    issue_chunk(sb, &g_w[WSLOT[1]][0], tid, 1);
    issue_chunk(sb, &g_w[WSLOT[2]][0], tid, 2);
    issue_chunk(sb, &g_w[WSLOT[3]][0], tid, 3);

    // bias -> smem
    float* bias = (float*)(smem + SM_BIAS);
    for (int i = tid; i < 768; i += THREADS) bias[i] = bias_g[i];

    // prologue: x, old_h -> fp16 tiles (each thread: 1 row x 32 cols)
    {
        int prow = tid >> 2, half = (tid & 3) * 32;
        const float4* px = (const float4*)(x    + ((size_t)tile * 128 + prow) * 128 + half);
        const float4* ph = (const float4*)(h_in + ((size_t)tile * 128 + prow) * 128 + half);
#pragma unroll
        for (int c4 = 0; c4 < 8; c4++) {
            float4 v = px[c4];
            sts_f(sb + SM_X, prow, half + c4 * 4,     make_float2(v.x, v.y));
            sts_f(sb + SM_X, prow, half + c4 * 4 + 2, make_float2(v.z, v.w));
            float4 u = ph[c4];
            sts_f(sb + SM_H, prow, half + c4 * 4,     make_float2(u.x, u.y));
            sts_f(sb + SM_H, prow, half + c4 * 4 + 2, make_float2(u.z, u.w));
        }
    }

    // per-thread ldmatrix base offsets (bytes within a tile)
    int aro = (lane & 7) + ((lane >> 3) & 1) * 8;
    int ako = ((lane >> 4) & 1) * 8;
    int bro = (lane & 7) + ((lane >> 4) & 1) * 8;
    int bko = ((lane >> 3) & 1) * 8;
    uint32_t aoff = (uint32_t)(((wm * 32 + aro) * AST + ako) * 2);
    uint32_t boff = (uint32_t)(((wn * 32 + bro) * AST + bko) * 2);

    uint32_t AX = sb + SM_X + aoff;
    uint32_t AH = sb + SM_H + aoff;
    uint32_t W0 = sb + SM_WBASE + 0 * TILE_BYTES + boff;
    uint32_t W1 = sb + SM_WBASE + 1 * TILE_BYTES + boff;
    uint32_t W2 = sb + SM_WBASE + 2 * TILE_BYTES + boff;
    uint32_t W3 = sb + SM_WBASE + 3 * TILE_BYTES + boff;

    float accA[2][4][4], accB[2][4][4];
    __half2 zreg[16];    // z gate, thread-private (producer == consumer coords)

    // epilogue element coordinates
    int erow = wm * 32 + (lane >> 2);        // + i*16 (+8 for regs 2,3)
    int ecol = wn * 32 + (lane & 3) * 2;     // + j*8
    float* otile = out + (size_t)tile * 128 * 128;

    // ---------------- R0: accA = x @ Wx1[2]  (c0/buf0) ----------------
    __syncthreads();
    WAITG3;
    zero_acc(accA);
    gemm_single(AX, W0, accA);

    // ---------------- R1: accB = x@Wx1[0] + h@Wh[0]  (c1/b1, c2/b2) ----------------
    __syncthreads();
    issue_chunk(sb, &g_w[WSLOT[4]][0], tid, 0);    // c4 -> buf0
    WAITG2;
    zero_acc(accB);
    gemm_dual(AX, W1, AH, W2, accB);
    // epi: z = sigmoid(accB + b0) -> zreg
#pragma unroll
    for (int i = 0; i < 2; i++)
#pragma unroll
        for (int j = 0; j < 4; j++) {
            int c = ecol + j * 8;
            zreg[i * 8 + j * 2 + 0] = __float22half2_rn(
                make_float2(sigm_f(accB[i][j][0] + bias[c]), sigm_f(accB[i][j][1] + bias[c + 1])));
            zreg[i * 8 + j * 2 + 1] = __float22half2_rn(
                make_float2(sigm_f(accB[i][j][2] + bias[c]), sigm_f(accB[i][j][3] + bias[c + 1])));
        }

    // ---------------- R2: accB = x@Wx1[1] + h@Wh[1]  (c3/b3, c4/b0) ----------------
    __syncthreads();
    issue_chunk(sb, &g_w[WSLOT[5]][0], tid, 1);    // c5 -> buf1
    issue_chunk(sb, &g_w[WSLOT[6]][0], tid, 2);    // c6 -> buf2
    WAITG2;
    zero_acc(accB);
    gemm_dual(AX, W3, AH, W0, accB);
    __syncthreads();   // region read X; epilogue writes X -> WAR sync
    // epi: r = sigmoid(accB + b1); rh = r * old_h -> X tile
#pragma unroll
    for (int i = 0; i < 2; i++)
#pragma unroll
        for (int j = 0; j < 4; j++) {
            int r0 = erow + i * 16, c = ecol + j * 8;
            float2 oh0 = lds_f(sb + SM_H, r0, c);
            float2 oh1 = lds_f(sb + SM_H, r0 + 8, c);
            sts_f(sb + SM_X, r0, c,
                  make_float2(sigm_f(accB[i][j][0] + bias[128 + c]) * oh0.x,
                              sigm_f(accB[i][j][1] + bias[128 + c + 1]) * oh0.y));
            sts_f(sb + SM_X, r0 + 8, c,
                  make_float2(sigm_f(accB[i][j][2] + bias[128 + c]) * oh1.x,
                              sigm_f(accB[i][j][3] + bias[128 + c + 1]) * oh1.y));
        }

    // ---------------- R3: accA += rh @ Wh[2]  (c5/b1) ----------------
    __syncthreads();
    issue_chunk(sb, &g_w[WSLOT[7]][0], tid, 3);    // c7 -> buf3
    WAITG2;
    gemm_single(AX, W1, accA);
    // epi: ht = tanh(accA + b2); mid_h = z*old_h + (1-z)*ht -> H tile (element-private)
#pragma unroll
    for (int i = 0; i < 2; i++)
#pragma unroll
        for (int j = 0; j < 4; j++) {
            int r0 = erow + i * 16, c = ecol + j * 8;
#pragma unroll
            for (int half = 0; half < 2; half++) {
                int r = r0 + half * 8;
                float2 oh = lds_f(sb + SM_H, r, c);
                float2 z  = __half22float2(zreg[i * 8 + j * 2 + half]);
                float ht0 = tanh_f(accA[i][j][2 * half]     + bias[256 + c]);
                float ht1 = tanh_f(accA[i][j][2 * half + 1] + bias[256 + c + 1]);
                sts_f(sb + SM_H, r, c,
                      make_float2(z.x * oh.x + (1.0f - z.x) * ht0,
                                  z.y * oh.y + (1.0f - z.y) * ht1));
            }
        }

    // ---------------- R4: accB = mid_h @ mid  (c6/b2) ----------------
    __syncthreads();
    issue_chunk(sb, &g_w[WSLOT[8]][0], tid, 0);    // c8 -> buf0
    WAITG2;
    zero_acc(accB);
    gemm_single(AH, W2, accB);
    // epi: mid_x = relu(accB) -> X tile (region read H; X writes safe)
#pragma unroll
    for (int i = 0; i < 2; i++)
#pragma unroll
        for (int j = 0; j < 4; j++) {
            int r0 = erow + i * 16, c = ecol + j * 8;
            sts_f(sb + SM_X, r0, c,
                  make_float2(fmaxf(accB[i][j][0], 0.0f), fmaxf(accB[i][j][1], 0.0f)));
            sts_f(sb + SM_X, r0 + 8, c,
                  make_float2(fmaxf(accB[i][j][2], 0.0f), fmaxf(accB[i][j][3], 0.0f)));
        }

    // ---------------- R5: accA = mid_x @ Wx2[2]  (c7/b3) ----------------
    __syncthreads();
    issue_chunk(sb, &g_w[WSLOT[9]][0], tid, 1);    // c9 -> buf1
    WAITG2;
    zero_acc(accA);
    gemm_single(AX, W3, accA);

    // ---------------- R6: accB = mid_x@Wx2[0] + mid_h@Wh[0]  (c8/b0, c9/b1) ----------------
    __syncthreads();
    issue_chunk(sb, &g_w[WSLOT[10]][0], tid, 2);   // c10 -> buf2
    issue_chunk(sb, &g_w[WSLOT[11]][0], tid, 3);   // c11 -> buf3
    WAITG2;
    zero_acc(accB);
    gemm_dual(AX, W0, AH, W1, accB);
    // epi: z2 = sigmoid(accB + b0) -> zreg
#pragma unroll
    for (int i = 0; i < 2; i++)
#pragma unroll
        for (int j = 0; j < 4; j++) {
            int c = ecol + j * 8;
            zreg[i * 8 + j * 2 + 0] = __float22half2_rn(
                make_float2(sigm_f(accB[i][j][0] + bias[c]), sigm_f(accB[i][j][1] + bias[c + 1])));
            zreg[i * 8 + j * 2 + 1] = __float22half2_rn(
                make_float2(sigm_f(accB[i][j][2] + bias[c]), sigm_f(accB[i][j][3] + bias[c + 1])));
        }

    // ---------------- R7: accB = mid_x@Wx2[1] + mid_h@Wh[4]  (c10/b2, c11/b3) ----------------
    __syncthreads();
    issue_chunk(sb, &g_w[WSLOT[12]][0], tid, 0);   // c12 -> buf0
    WAITG1;
    zero_acc(accB);
    gemm_dual(AX, W2, AH, W3, accB);
    __syncthreads();   // region read X; epilogue writes X -> WAR sync
    // epi: r2 = sigmoid(accB + b4); r2h = r2 * mid_h -> X tile
#pragma unroll
    for (int i = 0; i < 2; i++)
#pragma unroll
        for (int j = 0; j < 4; j++) {
            int r0 = erow + i * 16, c = ecol + j * 8;
            float2 mh0 = lds_f(sb + SM_H, r0, c);
            float2 mh1 = lds_f(sb + SM_H, r0 + 8, c);
            sts_f(sb + SM_X, r0, c,
                  make_float2(sigm_f(accB[i][j][0] + bias[512 + c]) * mh0.x,
                              sigm_f(accB[i][j][1] + bias[512 + c + 1]) * mh0.y));
            sts_f(sb + SM_X, r0 + 8, c,
                  make_float2(sigm_f(accB[i][j][2] + bias[512 + c]) * mh1.x,
                              sigm_f(accB[i][j][3] + bias[512 + c + 1]) * mh1.y));
        }

    // ---------------- R8: accA += r2h @ Wh[5]  (c12/b0) ----------------
    __syncthreads();
    WAITG0;
    gemm_single(AX, W0, accA);
    // final epi: h2t = tanh(accA + b5); h = z2*mid_h + (1-z2)*h2t -> OUT
#pragma unroll
    for (int i = 0; i < 2; i++)
#pragma unroll
        for (int j = 0; j < 4; j++) {
            int r0 = erow + i * 16, c = ecol + j * 8;
#pragma unroll
            for (int half = 0; half < 2; half++) {
                int r = r0 + half * 8;
                float2 mh = lds_f(sb + SM_H, r, c);
                float2 z  = __half22float2(zreg[i * 8 + j * 2 + half]);
                float t0 = tanh_f(accA[i][j][2 * half]     + bias[640 + c]);
                float t1 = tanh_f(accA[i][j][2 * half + 1] + bias[640 + c + 1]);
                float2 h = make_float2(z.x * mh.x + (1.0f - z.x) * t0,
                                       z.y * mh.y + (1.0f - z.y) * t1);
                *(float2*)(otile + (size_t)r * 128 + c) = h;
            }
        }
}

// ================================ launch ================================
extern "C" void kernel_launch(void* const* d_in, const int* in_sizes, int n_in,
                              void* d_out, int out_size) {
    const float* x   = (const float*)d_in[0];
    const float* oh  = (const float*)d_in[1];
    const float* wx1 = (const float*)d_in[2];
    const float* wx2 = (const float*)d_in[3];
    const float* wh  = (const float*)d_in[4];
    const float* b   = (const float*)d_in[5];
    const float* mid = (const float*)d_in[6];
    float* out = (float*)d_out;

    cudaFuncSetAttribute(dgru_kernel, cudaFuncAttributeMaxDynamicSharedMemorySize, SM_TOTAL);
    prep_weights<<<(13 * 128 * AST + 255) / 256, 256>>>(wx1, wx2, wh, mid);
    dgru_kernel<<<NTILES, THREADS, SM_TOTAL>>>(x, oh, b, out);
}

// round 16
// speedup vs baseline: 1.0578x; 1.0216x over previous
#include <cuda_runtime.h>
#include <cuda_fp16.h>
#include <cstdint>

// ============================================================================
// DoubleGRU on sm_100 (portable ISA): 13 chained GEMMs per tile using
// mma.sync.m16n8k16 fp16 (fp32 accum).
// R15: 64-row tiles, 256 threads, 2 CTAs/SM -> cross-CTA overlap of the
// serial epilogue/sync scaffold with the other CTA's MMAs. R12-proven k-loop,
// 1 sync per GEMM, ping-pong weight buffers, z gates in registers.
// ============================================================================

#define THREADS 256
#define NTILES  2048
#define AST     136                   // tile stride (fp16 elems, padded)
#define A_TILE_BYTES (64 * AST * 2)   // 17408 (activation tiles, 64 rows)
#define W_TILE_BYTES (128 * AST * 2)  // 34816 (weight tiles, full 128x128)

// ---- smem layout (bytes) ----
#define SM_BIAS 0                         // 768 floats
#define SM_X    4096
#define SM_H    (SM_X + A_TILE_BYTES)     // 21504
#define SM_W0   (SM_H + A_TILE_BYTES)     // 38912
#define SM_W1   (SM_W0 + W_TILE_BYTES)    // 73728
#define SM_TOTAL (SM_W1 + W_TILE_BYTES)   // 108544  (x2 CTAs = 217088 <= 227KB)

// GEMM g uses weight slot WSLOT[g] (R12-proven schedule).
// slots: 0-2 Wx1[i], 3-5 Wx2[i], 6-11 Wh[i], 12 mid
__device__ constexpr int WSLOT[13] = {2, 0, 6, 1, 7, 8, 12, 5, 3, 6, 4, 10, 11};

// Pre-transposed ([n][k], padded to AST) fp16 weight images.
__device__ __align__(256) __half g_w[13][128 * AST];

// ============================== PTX helpers ==============================
__device__ __forceinline__ uint32_t smem_to_u32(const void* p) {
    uint32_t a;
    asm("{ .reg .u64 t; cvta.to.shared.u64 t, %1; cvt.u32.u64 %0, t; }" : "=r"(a) : "l"(p));
    return a;
}

#define WAITG1 asm volatile("cp.async.wait_group 1;" ::: "memory")
#define WAITG0 asm volatile("cp.async.wait_group 0;" ::: "memory")
#define COMMITG asm volatile("cp.async.commit_group;" ::: "memory")

__device__ __forceinline__ void cp_async16(uint32_t dst, const void* src) {
    asm volatile("cp.async.cg.shared.global [%0], [%1], 16;" :: "r"(dst), "l"(src) : "memory");
}

__device__ __forceinline__ void ldm4(uint32_t* r, uint32_t addr) {
    asm volatile("ldmatrix.sync.aligned.m8n8.x4.shared.b16 {%0,%1,%2,%3}, [%4];"
        : "=r"(r[0]), "=r"(r[1]), "=r"(r[2]), "=r"(r[3]) : "r"(addr));
}

__device__ __forceinline__ void mma16816(float* c, const uint32_t* a, const uint32_t* b) {
    asm volatile("mma.sync.aligned.m16n8k16.row.col.f32.f16.f16.f32 "
        "{%0,%1,%2,%3}, {%4,%5,%6,%7}, {%8,%9}, {%0,%1,%2,%3};"
        : "+f"(c[0]), "+f"(c[1]), "+f"(c[2]), "+f"(c[3])
        : "r"(a[0]), "r"(a[1]), "r"(a[2]), "r"(a[3]), "r"(b[0]), "r"(b[1]));
}

// ============================== small math ==============================
__device__ __forceinline__ float tanh_f(float v) {
    float r;
    asm("tanh.approx.f32 %0, %1;" : "=f"(r) : "f"(v));
    return r;
}
__device__ __forceinline__ float sigm_f(float v) {
    return fmaf(tanh_f(v * 0.5f), 0.5f, 0.5f);
}
__device__ __forceinline__ float2 h2f(uint32_t u) {
    __half2 t = *reinterpret_cast<__half2*>(&u);
    return __half22float2(t);
}

// fp16 tile: load/store fp32 pair (col even)
__device__ __forceinline__ float2 lds_f(uint32_t base, int row, int col) {
    uint32_t off = (uint32_t)((row * AST + col) * 2);
    uint32_t h;
    asm volatile("ld.shared.u32 %0, [%1];" : "=r"(h) : "r"(base + off));
    return h2f(h);
}
__device__ __forceinline__ void sts_f(uint32_t base, int row, int col, float2 v) {
    __half2 hb = __float22half2_rn(v);
    uint32_t off = (uint32_t)((row * AST + col) * 2);
    uint32_t hu = *reinterpret_cast<uint32_t*>(&hb);
    asm volatile("st.shared.u32 [%0], %1;" :: "r"(base + off), "r"(hu) : "memory");
}

// ======================= weight prep (fp32 -> fp16, [n][k] padded) =======================
__global__ void prep_weights(const float* __restrict__ wx1, const float* __restrict__ wx2,
                             const float* __restrict__ wh, const float* __restrict__ mid) {
    int idx = blockIdx.x * blockDim.x + threadIdx.x;
    if (idx >= 13 * 128 * AST) return;
    int slot = idx / (128 * AST);
    int r = idx % (128 * AST);
    int n = r / AST;
    int k = r % AST;
    float v = 0.0f;
    if (k < 128) {
        const float* src;
        if (slot < 3)       src = wx1 + slot * 16384;
        else if (slot < 6)  src = wx2 + (slot - 3) * 16384;
        else if (slot < 12) src = wh + (slot - 6) * 16384;
        else                src = mid;
        v = src[k * 128 + n];   // W[k][n] -> B[n][k]
    }
    g_w[slot][n * AST + k] = __float2half_rn(v);
}

// ======================= GEMM (m32n32 warp tile, R12 core) =======================
__device__ __forceinline__ void gemm_single(uint32_t aT, uint32_t bB, float (*acc)[4][4]) {
#pragma unroll
    for (int k = 0; k < 8; k++) {
        uint32_t A0[4], A1[4], B0[4], B1[4];
        ldm4(A0, aT + k * 32);
        ldm4(A1, aT + 16 * AST * 2 + k * 32);
        ldm4(B0, bB + k * 32);
        ldm4(B1, bB + 16 * AST * 2 + k * 32);
        mma16816(acc[0][0], A0, B0);
        mma16816(acc[0][1], A0, B0 + 2);
        mma16816(acc[0][2], A0, B1);
        mma16816(acc[0][3], A0, B1 + 2);
        mma16816(acc[1][0], A1, B0);
        mma16816(acc[1][1], A1, B0 + 2);
        mma16816(acc[1][2], A1, B1);
        mma16816(acc[1][3], A1, B1 + 2);
    }
}

__device__ __forceinline__ void issue_chunk(uint32_t sb, const __half* src,
                                            int tid, int buf) {
    uint32_t dst = sb + (buf ? SM_W1 : SM_W0);
    const char* g = (const char*)src;
#pragma unroll
    for (int off = 0; off < W_TILE_BYTES; off += THREADS * 16) {
        int o = off + tid * 16;
        if (o < W_TILE_BYTES) cp_async16(dst + o, g + o);
    }
    COMMITG;
}

__device__ __forceinline__ void zero_acc(float (*acc)[4][4]) {
#pragma unroll
    for (int i = 0; i < 2; i++)
#pragma unroll
        for (int j = 0; j < 4; j++)
#pragma unroll
            for (int e = 0; e < 4; e++) acc[i][j][e] = 0.0f;
}

// ================================ main kernel ================================
__global__ void __launch_bounds__(THREADS, 2)
dgru_kernel(const float* __restrict__ x, const float* __restrict__ h_in,
            const float* __restrict__ bias_g, float* __restrict__ out) {
    extern __shared__ char smem[];
    uint32_t sb = smem_to_u32(smem);
    int tid  = threadIdx.x;
    int lane = tid & 31;
    int wid  = tid >> 5;
    int wm   = wid & 1;    // warp m block (32 rows of 64)
    int wn   = wid >> 1;   // warp n block (32 cols of 128)
    int tile = blockIdx.x;

    // kick off first two weight chunks immediately (chunk g -> buf g&1)
    issue_chunk(sb, &g_w[WSLOT[0]][0], tid, 0);
    issue_chunk(sb, &g_w[WSLOT[1]][0], tid, 1);

    // bias -> smem
    float* bias = (float*)(smem + SM_BIAS);
    for (int i = tid; i < 768; i += THREADS) bias[i] = bias_g[i];

    // prologue: x, old_h -> fp16 tiles (each thread: 1 row x 32 cols)
    {
        int prow = tid >> 2, half = (tid & 3) * 32;
        const float4* px = (const float4*)(x    + ((size_t)tile * 64 + prow) * 128 + half);
        const float4* ph = (const float4*)(h_in + ((size_t)tile * 64 + prow) * 128 + half);
#pragma unroll
        for (int c4 = 0; c4 < 8; c4++) {
            float4 v = px[c4];
            sts_f(sb + SM_X, prow, half + c4 * 4,     make_float2(v.x, v.y));
            sts_f(sb + SM_X, prow, half + c4 * 4 + 2, make_float2(v.z, v.w));
            float4 u = ph[c4];
            sts_f(sb + SM_H, prow, half + c4 * 4,     make_float2(u.x, u.y));
            sts_f(sb + SM_H, prow, half + c4 * 4 + 2, make_float2(u.z, u.w));
        }
    }

    // per-thread ldmatrix base offsets (bytes within a tile)
    int aro = (lane & 7) + ((lane >> 3) & 1) * 8;
    int ako = ((lane >> 4) & 1) * 8;
    int bro = (lane & 7) + ((lane >> 4) & 1) * 8;
    int bko = ((lane >> 3) & 1) * 8;
    uint32_t aoff = (uint32_t)(((wm * 32 + aro) * AST + ako) * 2);
    uint32_t boff = (uint32_t)(((wn * 32 + bro) * AST + bko) * 2);

    float accA[2][4][4], accB[2][4][4];
    __half2 zreg[8];     // z gate rows r0   (acc regs 0,1), thread-private
    __half2 zreg2[8];    // z gate rows r0+8 (acc regs 2,3), thread-private

    // epilogue element coordinates
    int erow = wm * 32 + (lane >> 2);        // + i*16 (+8 for regs 2,3)
    int ecol = wn * 32 + (lane & 3) * 2;     // + j*8
    float* otile = out + (size_t)tile * 64 * 128;

    // One GEMM per step, ONE sync per step (R12-proven protocol). Entry sync
    // proves all warps finished GEMM g-1 (which read buf (g+1)&1), so refill
    // that buffer with chunk g+1 here, then wait for chunk g (one group back).
#define GEMM_STEP(ACC, ATILE, G) do {                                           \
        __syncthreads();                                                        \
        if ((G) >= 1 && (G) <= 11) issue_chunk(sb, &g_w[WSLOT[(G) + 1]][0], tid, ((G) + 1) & 1); \
        if ((G) < 12) { WAITG1; } else { WAITG0; }                              \
        gemm_single(sb + (ATILE) + aoff,                                        \
                    sb + (((G) & 1) ? SM_W1 : SM_W0) + boff, ACC);              \
    } while (0)

    // ---------------- stage 1 ----------------
    zero_acc(accA);
    GEMM_STEP(accA, SM_X, 0);            // A  = x @ Wx1[2]
    zero_acc(accB);
    GEMM_STEP(accB, SM_X, 1);            // B  = x @ Wx1[0]
    GEMM_STEP(accB, SM_H, 2);            // B += h @ Wh[0]
    // epi: z = sigmoid(B + b0) -> zreg/zreg2
#pragma unroll
    for (int i = 0; i < 2; i++)
#pragma unroll
        for (int j = 0; j < 4; j++) {
            int c = ecol + j * 8;
            zreg[i * 4 + j] = __float22half2_rn(
                make_float2(sigm_f(accB[i][j][0] + bias[c]),
                            sigm_f(accB[i][j][1] + bias[c + 1])));
            zreg2[i * 4 + j] = __float22half2_rn(
                make_float2(sigm_f(accB[i][j][2] + bias[c]),
                            sigm_f(accB[i][j][3] + bias[c + 1])));
        }

    zero_acc(accB);
    GEMM_STEP(accB, SM_X, 3);            // B  = x @ Wx1[1]
    GEMM_STEP(accB, SM_H, 4);            // B += h @ Wh[1]
    // epi: r = sigmoid(B + b1); rh = r * old_h -> X tile
#pragma unroll
    for (int i = 0; i < 2; i++)
#pragma unroll
        for (int j = 0; j < 4; j++) {
            int r0 = erow + i * 16, c = ecol + j * 8;
            float2 oh0 = lds_f(sb + SM_H, r0, c);
            float2 oh1 = lds_f(sb + SM_H, r0 + 8, c);
            sts_f(sb + SM_X, r0, c,
                  make_float2(sigm_f(accB[i][j][0] + bias[128 + c]) * oh0.x,
                              sigm_f(accB[i][j][1] + bias[128 + c + 1]) * oh0.y));
            sts_f(sb + SM_X, r0 + 8, c,
                  make_float2(sigm_f(accB[i][j][2] + bias[128 + c]) * oh1.x,
                              sigm_f(accB[i][j][3] + bias[128 + c + 1]) * oh1.y));
        }

    GEMM_STEP(accA, SM_X, 5);            // A += rh @ Wh[2]
    // epi: ht = tanh(A + b2); z from zreg; mid_h = z*oh + (1-z)*ht -> H tile
#pragma unroll
    for (int i = 0; i < 2; i++)
#pragma unroll
        for (int j = 0; j < 4; j++) {
            int r0 = erow + i * 16, c = ecol + j * 8;
            {
                float2 oh = lds_f(sb + SM_H, r0, c);
                float2 z  = __half22float2(zreg[i * 4 + j]);
                float ht0 = tanh_f(accA[i][j][0] + bias[256 + c]);
                float ht1 = tanh_f(accA[i][j][1] + bias[256 + c + 1]);
                sts_f(sb + SM_H, r0, c,
                      make_float2(z.x * oh.x + (1.0f - z.x) * ht0,
                                  z.y * oh.y + (1.0f - z.y) * ht1));
            }
            {
                float2 oh = lds_f(sb + SM_H, r0 + 8, c);
                float2 z  = __half22float2(zreg2[i * 4 + j]);
                float ht0 = tanh_f(accA[i][j][2] + bias[256 + c]);
                float ht1 = tanh_f(accA[i][j][3] + bias[256 + c + 1]);
                sts_f(sb + SM_H, r0 + 8, c,
                      make_float2(z.x * oh.x + (1.0f - z.x) * ht0,
                                  z.y * oh.y + (1.0f - z.y) * ht1));
            }
        }

    zero_acc(accA);
    GEMM_STEP(accA, SM_H, 6);            // A = mid_h @ mid
    // epi: mid_x = relu(A) -> X tile
#pragma unroll
    for (int i = 0; i < 2; i++)
#pragma unroll
        for (int j = 0; j < 4; j++) {
            int r0 = erow + i * 16, c = ecol + j * 8;
            sts_f(sb + SM_X, r0, c,
                  make_float2(fmaxf(accA[i][j][0], 0.0f), fmaxf(accA[i][j][1], 0.0f)));
            sts_f(sb + SM_X, r0 + 8, c,
                  make_float2(fmaxf(accA[i][j][2], 0.0f), fmaxf(accA[i][j][3], 0.0f)));
        }

    // ---------------- stage 2 ----------------
    zero_acc(accA);
    GEMM_STEP(accA, SM_X, 7);            // A  = mid_x @ Wx2[2]
    zero_acc(accB);
    GEMM_STEP(accB, SM_X, 8);            // B  = mid_x @ Wx2[0]
    GEMM_STEP(accB, SM_H, 9);            // B += mid_h @ Wh[0]
    // epi: z2 = sigmoid(B + b0) -> zreg/zreg2
#pragma unroll
    for (int i = 0; i < 2; i++)
#pragma unroll
        for (int j = 0; j < 4; j++) {
            int c = ecol + j * 8;
            zreg[i * 4 + j] = __float22half2_rn(
                make_float2(sigm_f(accB[i][j][0] + bias[c]),
                            sigm_f(accB[i][j][1] + bias[c + 1])));
            zreg2[i * 4 + j] = __float22half2_rn(
                make_float2(sigm_f(accB[i][j][2] + bias[c]),
                            sigm_f(accB[i][j][3] + bias[c + 1])));
        }

    zero_acc(accB);
    GEMM_STEP(accB, SM_X, 10);           // B  = mid_x @ Wx2[1]
    GEMM_STEP(accB, SM_H, 11);           // B += mid_h @ Wh[4]
    // epi: r2 = sigmoid(B + b4); r2h = r2 * mid_h -> X tile
#pragma unroll
    for (int i = 0; i < 2; i++)
#pragma unroll
        for (int j = 0; j < 4; j++) {
            int r0 = erow + i * 16, c = ecol + j * 8;
            float2 mh0 = lds_f(sb + SM_H, r0, c);
            float2 mh1 = lds_f(sb + SM_H, r0 + 8, c);
            sts_f(sb + SM_X, r0, c,
                  make_float2(sigm_f(accB[i][j][0] + bias[512 + c]) * mh0.x,
                              sigm_f(accB[i][j][1] + bias[512 + c + 1]) * mh0.y));
            sts_f(sb + SM_X, r0 + 8, c,
                  make_float2(sigm_f(accB[i][j][2] + bias[512 + c]) * mh1.x,
                              sigm_f(accB[i][j][3] + bias[512 + c + 1]) * mh1.y));
        }

    GEMM_STEP(accA, SM_X, 12);           // A += r2h @ Wh[5]
    // final epi: h2t = tanh(A + b5); z2 from zreg; h = z2*mid_h + (1-z2)*h2t -> OUT
#pragma unroll
    for (int i = 0; i < 2; i++)
#pragma unroll
        for (int j = 0; j < 4; j++) {
            int r0 = erow + i * 16, c = ecol + j * 8;
            {
                float2 mh = lds_f(sb + SM_H, r0, c);
                float2 z  = __half22float2(zreg[i * 4 + j]);
                float t0 = tanh_f(accA[i][j][0] + bias[640 + c]);
                float t1 = tanh_f(accA[i][j][1] + bias[640 + c + 1]);
                *(float2*)(otile + (size_t)r0 * 128 + c) =
                    make_float2(z.x * mh.x + (1.0f - z.x) * t0,
                                z.y * mh.y + (1.0f - z.y) * t1);
            }
            {
                float2 mh = lds_f(sb + SM_H, r0 + 8, c);
                float2 z  = __half22float2(zreg2[i * 4 + j]);
                float t0 = tanh_f(accA[i][j][2] + bias[640 + c]);
                float t1 = tanh_f(accA[i][j][3] + bias[640 + c + 1]);
                *(float2*)(otile + (size_t)(r0 + 8) * 128 + c) =
                    make_float2(z.x * mh.x + (1.0f - z.x) * t0,
                                z.y * mh.y + (1.0f - z.y) * t1);
            }
        }
#undef GEMM_STEP
}

// ================================ launch ================================
extern "C" void kernel_launch(void* const* d_in, const int* in_sizes, int n_in,
                              void* d_out, int out_size) {
    const float* x   = (const float*)d_in[0];
    const float* oh  = (const float*)d_in[1];
    const float* wx1 = (const float*)d_in[2];
    const float* wx2 = (const float*)d_in[3];
    const float* wh  = (const float*)d_in[4];
    const float* b   = (const float*)d_in[5];
    const float* mid = (const float*)d_in[6];
    float* out = (float*)d_out;

    cudaFuncSetAttribute(dgru_kernel, cudaFuncAttributeMaxDynamicSharedMemorySize, SM_TOTAL);
    prep_weights<<<(13 * 128 * AST + 255) / 256, 256>>>(wx1, wx2, wh, mid);
    dgru_kernel<<<NTILES, THREADS, SM_TOTAL>>>(x, oh, b, out);
}